// round 3
// baseline (speedup 1.0000x reference)
#include <cuda_runtime.h>

// Problem constants
#define LL   1024   // sequence length
#define DM   768    // d_model
#define NH   12     // heads
#define FD   16     // feature dim per head
#define HD   64     // head dim (v)
#define CH   64     // chunk length
#define NC   16     // number of chunks (LL/CH)
#define DP   288    // padded expanded feature dim (273 -> 288)
#define CHUNK_ELT (DP*HD)   // 18432 floats per (head,chunk) state

// Scratch (static device globals; no allocation)
__device__ float g_Q   [LL * NH * FD];        // (t, h*16+f)
__device__ float g_K   [LL * NH * FD];
__device__ float g_V   [LL * DM];             // (t, h*64+d)
__device__ float g_Qf  [NH * NC * CHUNK_ELT]; // [h][c][n][i]  n=feature, i=token-in-chunk
__device__ float g_Kf  [NH * NC * CHUNK_ELT];
__device__ float g_S   [NH * NC * CHUNK_ELT]; // per-chunk KV sums -> exclusive prefix
__device__ float g_ksum[NH * NC * DP];        // per-chunk k-feature sums -> exclusive prefix
__device__ float g_Y   [LL * DM];             // attention output before Wo

// ---------------------------------------------------------------------------
// Generic 64x64 SGEMM body: C[M x N] = A[M x K] @ B[K x N], all row-major.
// 256 threads, 4x4 microtile, BK=16. M is blockIdx.y*64 (M=1024 always here).
// ---------------------------------------------------------------------------
__device__ __forceinline__ void sgemm_body(const float* __restrict__ A,
                                           const float* __restrict__ B,
                                           float* __restrict__ C,
                                           int N, int K) {
    __shared__ float As[16][65];                  // [k][m], padded vs conflicts
    __shared__ __align__(16) float Bs[16][64];    // [k][n]
    const int tid = threadIdx.x;
    const int ty = tid >> 4, tx = tid & 15;
    const int bm = blockIdx.y * 64, bn = blockIdx.x * 64;
    float acc[4][4] = {};
    for (int k0 = 0; k0 < K; k0 += 16) {
#pragma unroll
        for (int l = 0; l < 4; l++) {
            int idx = tid + l * 256;
            int r = idx >> 4, cc = idx & 15;
            As[cc][r] = A[(bm + r) * K + k0 + cc];
        }
#pragma unroll
        for (int l = 0; l < 4; l++) {
            int idx = tid + l * 256;
            int r = idx >> 6, cc = idx & 63;
            Bs[r][cc] = B[(k0 + r) * N + bn + cc];
        }
        __syncthreads();
#pragma unroll
        for (int kk = 0; kk < 16; kk++) {
            float a0 = As[kk][ty * 4 + 0];
            float a1 = As[kk][ty * 4 + 1];
            float a2 = As[kk][ty * 4 + 2];
            float a3 = As[kk][ty * 4 + 3];
            float4 b4 = *(const float4*)&Bs[kk][tx * 4];
            acc[0][0] += a0 * b4.x; acc[0][1] += a0 * b4.y; acc[0][2] += a0 * b4.z; acc[0][3] += a0 * b4.w;
            acc[1][0] += a1 * b4.x; acc[1][1] += a1 * b4.y; acc[1][2] += a1 * b4.z; acc[1][3] += a1 * b4.w;
            acc[2][0] += a2 * b4.x; acc[2][1] += a2 * b4.y; acc[2][2] += a2 * b4.z; acc[2][3] += a2 * b4.w;
            acc[3][0] += a3 * b4.x; acc[3][1] += a3 * b4.y; acc[3][2] += a3 * b4.z; acc[3][3] += a3 * b4.w;
        }
        __syncthreads();
    }
#pragma unroll
    for (int m = 0; m < 4; m++) {
        float4 o = make_float4(acc[m][0], acc[m][1], acc[m][2], acc[m][3]);
        *(float4*)&C[(bm + ty * 4 + m) * N + bn + tx * 4] = o;
    }
}

__global__ __launch_bounds__(256) void gemm_q_k(const float* __restrict__ hs, const float* __restrict__ W) {
    sgemm_body(hs, W, g_Q, NH * FD, DM);
}
__global__ __launch_bounds__(256) void gemm_k_k(const float* __restrict__ hs, const float* __restrict__ W) {
    sgemm_body(hs, W, g_K, NH * FD, DM);
}
__global__ __launch_bounds__(256) void gemm_v_k(const float* __restrict__ hs, const float* __restrict__ W) {
    sgemm_body(hs, W, g_V, DM, DM);
}
__global__ __launch_bounds__(256) void gemm_o_k(const float* __restrict__ W, float* __restrict__ out) {
    sgemm_body(g_Y, W, out, DM, DM);
}

// ---------------------------------------------------------------------------
// Featurize: taylor_exp_feature_map. Per (chunk, head) block writes the
// transposed chunk tile  dst[h][c][n][i]  (n = 0..287, i = token in chunk).
// n=0 -> 1 ; 1..16 -> x/2 ; 17..272 -> x_a*x_b / (4*sqrt(2)) ; 273..287 -> 0
// ---------------------------------------------------------------------------
__global__ __launch_bounds__(256) void featurize_k(int which) {
    const float* __restrict__ src = which ? g_K : g_Q;
    float* __restrict__ dst = which ? g_Kf : g_Qf;
    const int c = blockIdx.x, h = blockIdx.y;
    __shared__ float xs[64][17];
    const int tid = threadIdx.x;
    for (int idx = tid; idx < CH * FD; idx += 256) {
        int i = idx >> 4, f = idx & 15;
        xs[i][f] = src[(c * CH + i) * (NH * FD) + h * FD + f];
    }
    __syncthreads();
    float* out = dst + (h * NC + c) * CHUNK_ELT;
    const float S1 = 0.5f;                    // 1/RRD = 1/sqrt(sqrt(16))
    const float S2 = 0.17677669529663687f;    // 1/(sqrt(2)*sqrt(16))
    for (int idx = tid; idx < CHUNK_ELT; idx += 256) {
        int n = idx >> 6, i = idx & 63;
        float v;
        if (n == 0)        v = 1.0f;
        else if (n <= 16)  v = xs[i][n - 1] * S1;
        else if (n <= 272) { int p = n - 17; v = xs[i][p >> 4] * xs[i][p & 15] * S2; }
        else               v = 0.0f;
        out[idx] = v;
    }
}

// ---------------------------------------------------------------------------
// Per-chunk KV state: S[h][c][n][d] = sum_i Kf[h][c][n][i] * V[c*64+i][h*64+d]
// Also ksum[h][c][n] = sum_i Kf[n][i].  Grid: (3 n-tiles of 96, NC, NH).
// ---------------------------------------------------------------------------
__global__ __launch_bounds__(256) void chunk_kv_k() {
    const int nt = blockIdx.x, c = blockIdx.y, h = blockIdx.z;
    __shared__ __align__(16) float Ks[96 * 64];
    __shared__ __align__(16) float Vs[64 * 64];
    const int tid = threadIdx.x;
    const float* kf = g_Kf + ((h * NC + c) * DP + nt * 96) * 64;
    for (int idx = tid; idx < 96 * 64 / 4; idx += 256)
        ((float4*)Ks)[idx] = ((const float4*)kf)[idx];
    const float* vp = g_V + (c * CH) * DM + h * HD;
    for (int idx = tid; idx < 64 * 16; idx += 256) {
        int i = idx >> 4, dd = idx & 15;
        ((float4*)Vs)[i * 16 + dd] = ((const float4*)(vp + i * DM))[dd];
    }
    __syncthreads();
    const int ty = tid >> 4, tx = tid & 15;
    const int nb = ty * 6;
    float acc[6][4] = {};
    for (int i = 0; i < 64; i++) {
        float4 v4 = *(const float4*)&Vs[i * 64 + tx * 4];
#pragma unroll
        for (int m = 0; m < 6; m++) {
            float a = Ks[(nb + m) * 64 + i];
            acc[m][0] += a * v4.x; acc[m][1] += a * v4.y;
            acc[m][2] += a * v4.z; acc[m][3] += a * v4.w;
        }
    }
    float* sp = g_S + ((h * NC + c) * DP + nt * 96) * 64;
#pragma unroll
    for (int m = 0; m < 6; m++) {
        float4 o = make_float4(acc[m][0], acc[m][1], acc[m][2], acc[m][3]);
        *(float4*)&sp[(nb + m) * 64 + tx * 4] = o;
    }
    if (tid < 96) {
        float s = 0.f;
        for (int k = 0; k < 64; k++) s += Ks[tid * 64 + ((tid + k) & 63)];  // skewed: no bank conflicts
        g_ksum[(h * NC + c) * DP + nt * 96 + tid] = s;
    }
}

// ---------------------------------------------------------------------------
// Exclusive prefix over chunks (in place), for g_S and g_ksum.
// ---------------------------------------------------------------------------
__global__ __launch_bounds__(256) void prefix_k() {
    const int gid = blockIdx.x * 256 + threadIdx.x;
    const int NS = NH * CHUNK_ELT;  // 221184
    if (gid < NS) {
        int h = gid / CHUNK_ELT, e = gid % CHUNK_ELT;
        float* base = g_S + h * NC * CHUNK_ELT + e;
        float acc = 0.f;
#pragma unroll
        for (int c = 0; c < NC; c++) {
            float v = base[c * CHUNK_ELT];
            base[c * CHUNK_ELT] = acc;
            acc += v;
        }
    } else {
        int j = gid - NS;
        if (j < NH * DP) {
            int h = j / DP, n = j % DP;
            float* base = g_ksum + h * NC * DP + n;
            float acc = 0.f;
#pragma unroll
            for (int c = 0; c < NC; c++) {
                float v = base[c * DP];
                base[c * DP] = acc;
                acc += v;
            }
        }
    }
}

// ---------------------------------------------------------------------------
// Chunk attention: per (chunk, head) block.
//   A[i][j]   = sum_n Qf[n][i]*Kf[n][j]   (masked j<=i)
//   num[i][d] = sum_n Qf[n][i]*Sprev[n][d] + sum_j A[i][j]*V[j][d]
//   den[i]    = sum_n Qf[n][i]*ksumprev[n] + sum_j A[i][j]
//   Y[t][h*64+d] = num/(den+1e-12)
// Dynamic smem: Qs(72K) Ks(72K) Vs(16K) As(16K) = 180224 B.
// ---------------------------------------------------------------------------
__global__ __launch_bounds__(256) void chunk_attn_k() {
    const int c = blockIdx.x, h = blockIdx.y;
    extern __shared__ __align__(16) float sm[];
    float* Qs  = sm;                 // [n][i] 288x64
    float* Ks  = sm + CHUNK_ELT;     // [n][j] 288x64
    float* Vs  = sm + 2 * CHUNK_ELT; // [j][d] 64x64
    float* Asm = Vs + 64 * 64;       // [i][j] 64x64
    const int tid = threadIdx.x;

    const float* qf = g_Qf + (h * NC + c) * CHUNK_ELT;
    const float* kf = g_Kf + (h * NC + c) * CHUNK_ELT;
    for (int idx = tid; idx < CHUNK_ELT / 4; idx += 256) {
        ((float4*)Qs)[idx] = ((const float4*)qf)[idx];
        ((float4*)Ks)[idx] = ((const float4*)kf)[idx];
    }
    const float* vp = g_V + (c * CH) * DM + h * HD;
    for (int idx = tid; idx < 64 * 16; idx += 256) {
        int i = idx >> 4, dd = idx & 15;
        ((float4*)Vs)[i * 16 + dd] = ((const float4*)(vp + i * DM))[dd];
    }
    __syncthreads();

    const int ty = tid >> 4, tx = tid & 15;
    const int i0 = ty * 4, c0 = tx * 4;
    const float* Sx = g_S + (h * NC + c) * CHUNK_ELT;
    const float* kx = g_ksum + (h * NC + c) * DP;

    float aA[4][4] = {};   // QK^T scores (i x j)
    float aN[4][4] = {};   // numerator   (i x d)
    float aD[4] = {};      // denominator (i) -- computed redundantly per tx

#pragma unroll 2
    for (int n = 0; n < DP; n++) {
        float4 q4 = *(const float4*)&Qs[n * 64 + i0];
        float4 k4 = *(const float4*)&Ks[n * 64 + c0];
        float4 s4 = __ldg((const float4*)(Sx + n * 64 + c0));
        float ks  = __ldg(kx + n);
        float q[4] = { q4.x, q4.y, q4.z, q4.w };
        float kk[4] = { k4.x, k4.y, k4.z, k4.w };
        float ss[4] = { s4.x, s4.y, s4.z, s4.w };
#pragma unroll
        for (int m = 0; m < 4; m++) {
#pragma unroll
            for (int j = 0; j < 4; j++) {
                aA[m][j] += q[m] * kk[j];
                aN[m][j] += q[m] * ss[j];
            }
            aD[m] += q[m] * ks;
        }
    }

    // causal mask (j <= i keeps, inclusive diagonal) and stash to smem
#pragma unroll
    for (int m = 0; m < 4; m++) {
        int ig = i0 + m;
        float4 r;
        r.x = (c0 + 0 <= ig) ? aA[m][0] : 0.0f;
        r.y = (c0 + 1 <= ig) ? aA[m][1] : 0.0f;
        r.z = (c0 + 2 <= ig) ? aA[m][2] : 0.0f;
        r.w = (c0 + 3 <= ig) ? aA[m][3] : 0.0f;
        *(float4*)&Asm[ig * 64 + c0] = r;
    }
    __syncthreads();

    // intra-chunk: num += A @ V ; den += rowsum(A)
    for (int j = 0; j < 64; j++) {
        float4 v4 = *(const float4*)&Vs[j * 64 + c0];
#pragma unroll
        for (int m = 0; m < 4; m++) {
            float a = Asm[(i0 + m) * 64 + j];
            aN[m][0] += a * v4.x; aN[m][1] += a * v4.y;
            aN[m][2] += a * v4.z; aN[m][3] += a * v4.w;
            aD[m] += a;
        }
    }

    float* yp = g_Y + (c * CH) * DM + h * HD;
#pragma unroll
    for (int m = 0; m < 4; m++) {
        float inv = 1.0f / (aD[m] + 1e-12f);
        float4 o = make_float4(aN[m][0] * inv, aN[m][1] * inv,
                               aN[m][2] * inv, aN[m][3] * inv);
        *(float4*)&yp[(i0 + m) * DM + c0] = o;
    }
}

// ---------------------------------------------------------------------------
extern "C" void kernel_launch(void* const* d_in, const int* in_sizes, int n_in,
                              void* d_out, int out_size) {
    const float* hs = (const float*)d_in[0];
    const float* Wq = (const float*)d_in[1];
    const float* Wk = (const float*)d_in[2];
    const float* Wv = (const float*)d_in[3];
    const float* Wo = (const float*)d_in[4];
    float* out = (float*)d_out;

    const int attn_smem = (2 * CHUNK_ELT + 2 * 64 * 64) * 4;  // 180224 B
    cudaFuncSetAttribute(chunk_attn_k, cudaFuncAttributeMaxDynamicSharedMemorySize, attn_smem);

    dim3 thr(256);
    gemm_q_k<<<dim3(3, 16), thr>>>(hs, Wq);
    gemm_k_k<<<dim3(3, 16), thr>>>(hs, Wk);
    gemm_v_k<<<dim3(12, 16), thr>>>(hs, Wv);
    featurize_k<<<dim3(NC, NH), thr>>>(0);
    featurize_k<<<dim3(NC, NH), thr>>>(1);
    chunk_kv_k<<<dim3(3, NC, NH), thr>>>();
    {
        int total = NH * CHUNK_ELT + NH * DP;       // 224640
        prefix_k<<<(total + 255) / 256, 256>>>();
    }
    chunk_attn_k<<<dim3(NC, NH), thr, attn_smem>>>();
    gemm_o_k<<<dim3(12, 16), thr>>>(Wo, out);
}